// round 3
// baseline (speedup 1.0000x reference)
#include <cuda_runtime.h>

// out[b,s,e] = sum_h cs[b,s,e,h] * W[e,h] + bias[e]
// B=4, S=512, E=64, H=1024 -> ROWS = 131072 reductions over 1024 contiguous floats.
// HBM-bound streaming. R3: each warp handles 8 rows sharing the same entity e
// (rows q*64+e), processed in pairs: one W fetch serves 2 rows, 8KB of
// independent .cs loads in flight per pass, and the two warp-reduction chains
// interleave. 8x fewer CTAs -> amortized prologue/epilogue/churn.

#define E_DIM 64
#define HV4   256              // 1024 floats / 4
#define ROWS_PER_WARP 8
#define WARPS_PER_BLOCK 4

__device__ __forceinline__ float4 ldcs_f4(const float4* p) {
    float4 v;
    asm volatile("ld.global.cs.v4.f32 {%0,%1,%2,%3}, [%4];"
                 : "=f"(v.x), "=f"(v.y), "=f"(v.z), "=f"(v.w)
                 : "l"(p));
    return v;
}

__global__ __launch_bounds__(WARPS_PER_BLOCK * 32)
void Cell_to_Entity_78735340470739_kernel(
    const float4* __restrict__ cs,    // [ROWS, HV4]
    const float4* __restrict__ W,     // [E, HV4]
    const float*  __restrict__ bias,  // [E]
    float*        __restrict__ out)   // [ROWS]
{
    const int lane = threadIdx.x & 31;
    const int gw   = blockIdx.x * WARPS_PER_BLOCK + (threadIdx.x >> 5);

    const int e      = gw & (E_DIM - 1);            // entity: fixed per warp
    const int q_base = (gw >> 6) * ROWS_PER_WARP;   // 8 consecutive q's

    const float4* __restrict__ w = W + (size_t)e * HV4;
    const float be = __ldg(&bias[e]);

#pragma unroll 1
    for (int j = 0; j < ROWS_PER_WARP; j += 2) {
        const size_t row0 = (size_t)(q_base + j) * E_DIM + e;
        const float4* __restrict__ x0 = cs + row0 * HV4;
        const float4* __restrict__ x1 = x0 + (size_t)E_DIM * HV4;  // next q, same e

        float acc0 = 0.0f, acc1 = 0.0f;
#pragma unroll
        for (int i = 0; i < 8; ++i) {
            const int idx = lane + 32 * i;
            float4 wv = __ldg(&w[idx]);     // hot in L1 (one row reused 8x/warp)
            float4 a0 = ldcs_f4(&x0[idx]);  // streaming, evict-first
            float4 a1 = ldcs_f4(&x1[idx]);
            acc0 += a0.x * wv.x + a0.y * wv.y + a0.z * wv.z + a0.w * wv.w;
            acc1 += a1.x * wv.x + a1.y * wv.y + a1.z * wv.z + a1.w * wv.w;
        }

        // two independent reduction chains -> shuffles overlap
#pragma unroll
        for (int off = 16; off > 0; off >>= 1) {
            acc0 += __shfl_xor_sync(0xffffffffu, acc0, off);
            acc1 += __shfl_xor_sync(0xffffffffu, acc1, off);
        }

        if (lane == 0) {
            out[row0]                      = acc0 + be;
            out[row0 + E_DIM]              = acc1 + be;
        }
    }
}

extern "C" void kernel_launch(void* const* d_in, const int* in_sizes, int n_in,
                              void* d_out, int out_size)
{
    const float4* cs   = (const float4*)d_in[0];   // [B,S,E,H] float32
    const float4* W    = (const float4*)d_in[1];   // [E,H]     float32
    const float*  bias = (const float*)d_in[2];    // [E]       float32
    float*        out  = (float*)d_out;            // [B,S,E]   float32

    const int rows        = out_size;                          // 131072
    const int total_warps = rows / ROWS_PER_WARP;              // 16384
    const int blocks      = total_warps / WARPS_PER_BLOCK;     // 4096

    Cell_to_Entity_78735340470739_kernel<<<blocks, WARPS_PER_BLOCK * 32>>>(cs, W, bias, out);
}

// round 4
// speedup vs baseline: 1.0600x; 1.0600x over previous
#include <cuda_runtime.h>

// out[b,s,e] = sum_h cs[b,s,e,h] * W[e,h] + bias[e]
// B=4, S=512, E=64, H=1024 -> ROWS = 131072 reductions over 1024 contiguous floats.
// HBM-bound streaming: one warp per row (R2 structure — R3's 8-rows/warp
// regressed via reg pressure/occupancy). R4: 64-thread CTAs for finer
// occupancy granularity and smaller per-CTA L1tex load bursts (spread model).

#define E_DIM 64
#define H_DIM 1024
#define HV4   (H_DIM / 4)      // 256 float4 per row
#define WARPS_PER_BLOCK 2

__device__ __forceinline__ float4 ldcs_f4(const float4* p) {
    float4 v;
    asm volatile("ld.global.cs.v4.f32 {%0,%1,%2,%3}, [%4];"
                 : "=f"(v.x), "=f"(v.y), "=f"(v.z), "=f"(v.w)
                 : "l"(p));
    return v;
}

__global__ __launch_bounds__(WARPS_PER_BLOCK * 32)
void Cell_to_Entity_78735340470739_kernel(
    const float4* __restrict__ cs,    // [ROWS, HV4]
    const float4* __restrict__ W,     // [E, HV4]
    const float*  __restrict__ bias,  // [E]
    float*        __restrict__ out)   // [ROWS]
{
    const int warp = threadIdx.x >> 5;
    const int lane = threadIdx.x & 31;
    const int row  = blockIdx.x * WARPS_PER_BLOCK + warp;

    const int e = row & (E_DIM - 1);

    const float4* __restrict__ x = cs + (size_t)row * HV4;
    const float4* __restrict__ w = W  + (size_t)e   * HV4;

    float acc = 0.0f;
#pragma unroll
    for (int i = 0; i < 8; ++i) {
        const int idx = lane + 32 * i;
        float4 a = ldcs_f4(&x[idx]);   // streaming, evict-first: one-pass data
        float4 b = __ldg(&w[idx]);     // hot in L1/L2 (256 KiB total W)
        acc += a.x * b.x + a.y * b.y + a.z * b.z + a.w * b.w;
    }

    // warp reduction
#pragma unroll
    for (int off = 16; off > 0; off >>= 1)
        acc += __shfl_xor_sync(0xffffffffu, acc, off);

    if (lane == 0)
        out[row] = acc + __ldg(&bias[e]);
}

extern "C" void kernel_launch(void* const* d_in, const int* in_sizes, int n_in,
                              void* d_out, int out_size)
{
    const float4* cs   = (const float4*)d_in[0];   // [B,S,E,H] float32
    const float4* W    = (const float4*)d_in[1];   // [E,H]     float32
    const float*  bias = (const float*)d_in[2];    // [E]       float32
    float*        out  = (float*)d_out;            // [B,S,E]   float32

    const int rows   = out_size;                   // B*S*E = 131072
    const int blocks = rows / WARPS_PER_BLOCK;     // 65536

    Cell_to_Entity_78735340470739_kernel<<<blocks, WARPS_PER_BLOCK * 32>>>(cs, W, bias, out);
}